// round 14
// baseline (speedup 1.0000x reference)
#include <cuda_runtime.h>
#include <cstddef>
#include <cstdint>

// ---------------------------------------------------------------------------
// StokenAttention: B=8, C=256, H=W=128, 8x8 super-tokens -> 16x16 grid,
// NH=8 heads, HD=KD=32.
// GEMMs (qkv, proj) AND k_aff's two per-token GEMMs on mma.sync m16n8k16
// bf16 hi/lo (fp32-like accuracy). k_aff G1 B-operand via ldmatrix.trans.
// ---------------------------------------------------------------------------

#define Bb 8
#define Cc 256
#define GG 16
#define NT 256
#define NP 64
#define HW 16384
#define NH 8
#define HD 32
#define NTOK (Bb * NT)

__device__ float g_stoken[NTOK * Cc];
__device__ float g_aff[NTOK * NP * 9];
__device__ float g_asum[NTOK * 9];
__device__ float g_M[(size_t)NTOK * 9 * Cc];
__device__ float g_sf[NTOK * Cc];
__device__ float g_qkvt[(size_t)NTOK * 768];     // [tok][o] token-major
__device__ float g_tmp[NTOK * Cc];
__device__ float g_sfa[NTOK * Cc];

#define AFF_SCALE 0.0625f
#define ATTN_SCALE 0.17677669529663687f

// --------------------------- bf16 mma helpers ------------------------------
__device__ __forceinline__ void pack2(float x, float y, uint32_t& h, uint32_t& lo) {
    asm("cvt.rn.bf16x2.f32 %0, %1, %2;" : "=r"(h) : "f"(y), "f"(x));
    float xh = __uint_as_float(h << 16);
    float yh = __uint_as_float(h & 0xFFFF0000u);
    float xl = x - xh, yl = y - yh;
    asm("cvt.rn.bf16x2.f32 %0, %1, %2;" : "=r"(lo) : "f"(yl), "f"(xl));
}
__device__ __forceinline__ void splitbf(float v, uint16_t& h, uint16_t& lo) {
    asm("cvt.rn.bf16.f32 %0, %1;" : "=h"(h) : "f"(v));
    float vh = __uint_as_float((uint32_t)h << 16);
    asm("cvt.rn.bf16.f32 %0, %1;" : "=h"(lo) : "f"(v - vh));
}
__device__ __forceinline__ void mma16(float* c, const uint32_t* a, const uint32_t* b) {
    asm volatile(
        "mma.sync.aligned.m16n8k16.row.col.f32.bf16.bf16.f32 "
        "{%0,%1,%2,%3}, {%4,%5,%6,%7}, {%8,%9}, {%0,%1,%2,%3};"
        : "+f"(c[0]), "+f"(c[1]), "+f"(c[2]), "+f"(c[3])
        : "r"(a[0]), "r"(a[1]), "r"(a[2]), "r"(a[3]), "r"(b[0]), "r"(b[1]));
}
__device__ __forceinline__ void ldsm_x2_t(uint32_t& r0, uint32_t& r1, uint32_t addr) {
    asm volatile("ldmatrix.sync.aligned.m8n8.x2.trans.shared.b16 {%0,%1}, [%2];"
                 : "=r"(r0), "=r"(r1) : "r"(addr));
}
__device__ __forceinline__ uint32_t smem_u32(const void* p) {
    uint32_t a;
    asm("{ .reg .u64 t; cvta.to.shared.u64 t, %1; cvt.u32.u64 %0, t; }"
        : "=r"(a) : "l"(p));
    return a;
}

// ------------------------------- K1: pooling -------------------------------
__global__ void k_pool(const float* __restrict__ x) {
    int bt = blockIdx.x;
    int t = bt & 255;
    int ty = t >> 4, tx = t & 15;
    int c = threadIdx.x;
    const float* xp = x + (size_t)(((bt >> 8) * Cc + c)) * HW + (ty * 8) * 128 + tx * 8;
    float s = 0.f;
#pragma unroll
    for (int i = 0; i < 8; i++) {
        float4 a = *(const float4*)(xp + i * 128);
        float4 b4 = *(const float4*)(xp + i * 128 + 4);
        s += a.x + a.y + a.z + a.w + b4.x + b4.y + b4.z + b4.w;
    }
    g_stoken[bt * Cc + c] = s * (1.0f / 64.0f);
}

// ------------------------- K2: affinity + token GEMM (tensor) ---------------
// smem word offsets
#define KA_PIXH 0            // pix bf16-hi [c=256][p2=32] stride 36
#define KA_PIXL 9216
#define KA_ST9H 18432        // st9 bf16-hi [k=16][c2=128] stride 132
#define KA_ST9L 20544
#define KA_SM   22656        // S fp32 [p=64][k] stride 17
#define KA_AFF  23744        // aff fp32 [p=64][12]
#define KA_AFTH 24512        // affT bf16-hi [k=16][p2=32] stride 36
#define KA_AFTL 25088
#define KA_WORDS 25664
#define KA_SMEM (KA_WORDS * 4)

__global__ void k_aff(const float* __restrict__ x) {
    extern __shared__ uint32_t dsm[];
    uint32_t sbase = smem_u32(dsm);

    int bt = blockIdx.x;
    int b = bt >> 8, t = bt & 255;
    int ty = t >> 4, tx = t & 15;
    int tid = threadIdx.x;
    int w = tid >> 5, l = tid & 31;
    int g = l >> 2, tg = l & 3;

    // --- stage st9 as A operand [k16][c2], rows 9..15 zero ---
    for (int i = tid; i < 16 * 128; i += 256) {
        int k = i >> 7, c2 = i & 127;
        float v0 = 0.f, v1 = 0.f;
        if (k < 9) {
            int ny = ty + k / 3 - 1, nx = tx + k % 3 - 1;
            if ((unsigned)ny < GG && (unsigned)nx < GG) {
                const float* sp = g_stoken + (size_t)(b * NT + ny * GG + nx) * Cc + 2 * c2;
                v0 = sp[0]; v1 = sp[1];
            }
        }
        uint32_t h, lo;
        pack2(v0, v1, h, lo);
        dsm[KA_ST9H + k * 132 + c2] = h;
        dsm[KA_ST9L + k * 132 + c2] = lo;
    }
    // --- stage pix as [c][p2] bf16 hi/lo (sector-optimal loads) ---
    const float* xb = x + (size_t)b * Cc * HW + (ty * 8) * 128 + tx * 8;
#pragma unroll
    for (int it = 0; it < 16; it++) {
        int idx = tid + it * 256;
        int c = idx >> 4;
        int q = idx & 15;
        int sy = q >> 1, hx = q & 1;
        float4 v = *(const float4*)(xb + (size_t)c * HW + sy * 128 + hx * 4);
        int p2 = (sy * 8 + hx * 4) >> 1;
        uint32_t h, lo;
        pack2(v.x, v.y, h, lo);
        dsm[KA_PIXH + c * 36 + p2] = h;
        dsm[KA_PIXL + c * 36 + p2] = lo;
        pack2(v.z, v.w, h, lo);
        dsm[KA_PIXH + c * 36 + p2 + 1] = h;
        dsm[KA_PIXL + c * 36 + p2 + 1] = lo;
    }
    __syncthreads();

    // --- G1: C[k16][p64] = st9 x pix^T; warp w owns p-range [8w, 8w+8) ---
    {
        float accS[4] = {0.f, 0.f, 0.f, 0.f};
        int lrow = l & 15;
        uint32_t ldh = sbase + (uint32_t)(KA_PIXH + lrow * 36) * 4 + (8 * w) * 2;
        uint32_t ldl = ldh + (uint32_t)(KA_PIXL - KA_PIXH) * 4;
#pragma unroll
        for (int kt = 0; kt < 16; kt++) {
            uint32_t ah[4], al[4], bh[2], bl[2];
            int i0 = g * 132 + kt * 8 + tg;
            ah[0] = dsm[KA_ST9H + i0];        ah[1] = dsm[KA_ST9H + i0 + 1056];
            ah[2] = dsm[KA_ST9H + i0 + 4];    ah[3] = dsm[KA_ST9H + i0 + 1060];
            al[0] = dsm[KA_ST9L + i0];        al[1] = dsm[KA_ST9L + i0 + 1056];
            al[2] = dsm[KA_ST9L + i0 + 4];    al[3] = dsm[KA_ST9L + i0 + 1060];
            ldsm_x2_t(bh[0], bh[1], ldh + (uint32_t)kt * 16 * 144);
            ldsm_x2_t(bl[0], bl[1], ldl + (uint32_t)kt * 16 * 144);
            mma16(accS, ah, bh);
            mma16(accS, ah, bl);
            mma16(accS, al, bh);
        }
        float* Sm = (float*)(dsm + KA_SM);
        int pb = 8 * w + 2 * tg;
        Sm[pb * 17 + g] = accS[0];
        Sm[(pb + 1) * 17 + g] = accS[1];
        Sm[pb * 17 + g + 8] = accS[2];
        Sm[(pb + 1) * 17 + g + 8] = accS[3];
    }
    __syncthreads();

    // --- softmax per pixel + affT staging; zero affT rows 9..15 ---
    if (tid < 64) {
        float* Sm = (float*)(dsm + KA_SM);
        float* afff = (float*)(dsm + KA_AFF);
        uint16_t* ath = (uint16_t*)(dsm + KA_AFTH);
        uint16_t* atl = (uint16_t*)(dsm + KA_AFTL);
        float v[9];
        float mx = -1e30f;
#pragma unroll
        for (int k = 0; k < 9; k++) { v[k] = Sm[tid * 17 + k] * AFF_SCALE; mx = fmaxf(mx, v[k]); }
        float sum = 0.f;
#pragma unroll
        for (int k = 0; k < 9; k++) { v[k] = __expf(v[k] - mx); sum += v[k]; }
        float inv = 1.f / sum;
#pragma unroll
        for (int k = 0; k < 9; k++) {
            float a = v[k] * inv;
            afff[tid * 12 + k] = a;
            uint16_t hh, lo;
            splitbf(a, hh, lo);
            ath[k * 72 + tid] = hh;
            atl[k * 72 + tid] = lo;
        }
    } else {
        for (int i = tid - 64; i < 7 * 36; i += 192) {
            dsm[KA_AFTH + 9 * 36 + i] = 0;
            dsm[KA_AFTL + 9 * 36 + i] = 0;
        }
    }
    __syncthreads();

    // --- outputs: g_aff, g_asum ---
    {
        float* afff = (float*)(dsm + KA_AFF);
        for (int idx = tid; idx < 576; idx += 256) {
            int p = idx / 9, k = idx - p * 9;
            g_aff[bt * 576 + idx] = afff[p * 12 + k];
        }
        if (tid < 9) {
            float s = 0.f;
            for (int p = 0; p < 64; p++) s += afff[p * 12 + tid];
            g_asum[bt * 9 + tid] = s;
        }
    }

    // --- G2: M[k16][c256] = affT x pix; warp w owns c-range [32w, 32w+32) ---
    {
        uint32_t Ah[4][4], Al[4][4];
#pragma unroll
        for (int kt = 0; kt < 4; kt++) {
            int i0 = g * 36 + kt * 8 + tg;
            Ah[kt][0] = dsm[KA_AFTH + i0];       Ah[kt][1] = dsm[KA_AFTH + i0 + 288];
            Ah[kt][2] = dsm[KA_AFTH + i0 + 4];   Ah[kt][3] = dsm[KA_AFTH + i0 + 292];
            Al[kt][0] = dsm[KA_AFTL + i0];       Al[kt][1] = dsm[KA_AFTL + i0 + 288];
            Al[kt][2] = dsm[KA_AFTL + i0 + 4];   Al[kt][3] = dsm[KA_AFTL + i0 + 292];
        }
        float* Mo = g_M + (size_t)bt * 9 * Cc;
#pragma unroll
        for (int j = 0; j < 4; j++) {
            int cb = 32 * w + 8 * j;
            float acc[4] = {0.f, 0.f, 0.f, 0.f};
#pragma unroll
            for (int kt = 0; kt < 4; kt++) {
                uint32_t bh[2], bl[2];
                int bi = (cb + g) * 36 + kt * 8 + tg;
                bh[0] = dsm[KA_PIXH + bi]; bh[1] = dsm[KA_PIXH + bi + 4];
                bl[0] = dsm[KA_PIXL + bi]; bl[1] = dsm[KA_PIXL + bi + 4];
                mma16(acc, Ah[kt], bh);
                mma16(acc, Ah[kt], bl);
                mma16(acc, Al[kt], bh);
            }
            float2 v01; v01.x = acc[0]; v01.y = acc[1];
            *(float2*)(Mo + g * Cc + cb + 2 * tg) = v01;
            if (g == 0) {
                float2 v23; v23.x = acc[2]; v23.y = acc[3];
                *(float2*)(Mo + 8 * Cc + cb + 2 * tg) = v23;
            }
        }
    }
}

// ------------------------------- K3: fold ----------------------------------
__global__ void k_fold() {
    int bt = blockIdx.x;
    int b = bt >> 8, t = bt & 255;
    int y = t >> 4, x = t & 15;
    __shared__ float s_as;
    int tid = threadIdx.x;
    if (tid == 0) {
        float s = 0.f;
        for (int ny = y - 1; ny <= y + 1; ny++)
            for (int nx = x - 1; nx <= x + 1; nx++)
                if ((unsigned)ny < GG && (unsigned)nx < GG) {
                    int k = (y - ny + 1) * 3 + (x - nx + 1);
                    s += g_asum[(b * NT + ny * GG + nx) * 9 + k];
                }
        s_as = s + 1e-12f;
    }
    __syncthreads();
    int c = tid;
    float s = 0.f;
    for (int ny = y - 1; ny <= y + 1; ny++)
        for (int nx = x - 1; nx <= x + 1; nx++)
            if ((unsigned)ny < GG && (unsigned)nx < GG) {
                int k = (y - ny + 1) * 3 + (x - nx + 1);
                s += g_M[((size_t)(b * NT + ny * GG + nx) * 9 + k) * Cc + c];
            }
    g_sf[bt * Cc + c] = s / s_as;
}

// ---------- GEMM via mma.sync m16n8k16 bf16 (hi/lo, token-major out) --------
template <int MM>
__device__ __forceinline__ void gemm_mma_body(const float* __restrict__ A,
                                              const float* __restrict__ Bm,
                                              float* __restrict__ Cm) {
    const int K = 256;
    __shared__ uint32_t smx[2][4][1280];

    int bm = blockIdx.x * 64;
    int bn = blockIdx.y * 64;
    int tid = threadIdx.x;
    int w = tid >> 5, l = tid & 31;
    int wm = w >> 2, wn = w & 3;
    int g = l >> 2, tg = l & 3;

    int r0 = tid >> 3, r1 = r0 + 32;
    int k0q = (tid & 7) * 4;
    int k2s = k0q >> 1;

    const float* Ap0 = A + (size_t)(bm + r0) * K + k0q;
    const float* Ap1 = A + (size_t)(bm + r1) * K + k0q;
    const float* Bp0 = Bm + (size_t)(bn + r0) * K + k0q;
    const float* Bp1 = Bm + (size_t)(bn + r1) * K + k0q;

    float4 rA0, rA1, rB0, rB1;

    auto stage = [&](int buf, const float4& a0v, const float4& a1v,
                     const float4& b0v, const float4& b1v) {
        uint32_t h0, l0, h1, l1;
        pack2(a0v.x, a0v.y, h0, l0); pack2(a0v.z, a0v.w, h1, l1);
        *(uint2*)&smx[buf][0][r0 * 20 + k2s] = make_uint2(h0, h1);
        *(uint2*)&smx[buf][1][r0 * 20 + k2s] = make_uint2(l0, l1);
        pack2(a1v.x, a1v.y, h0, l0); pack2(a1v.z, a1v.w, h1, l1);
        *(uint2*)&smx[buf][0][r1 * 20 + k2s] = make_uint2(h0, h1);
        *(uint2*)&smx[buf][1][r1 * 20 + k2s] = make_uint2(l0, l1);
        pack2(b0v.x, b0v.y, h0, l0); pack2(b0v.z, b0v.w, h1, l1);
        *(uint2*)&smx[buf][2][r0 * 20 + k2s] = make_uint2(h0, h1);
        *(uint2*)&smx[buf][3][r0 * 20 + k2s] = make_uint2(l0, l1);
        pack2(b1v.x, b1v.y, h0, l0); pack2(b1v.z, b1v.w, h1, l1);
        *(uint2*)&smx[buf][2][r1 * 20 + k2s] = make_uint2(h0, h1);
        *(uint2*)&smx[buf][3][r1 * 20 + k2s] = make_uint2(l0, l1);
    };

    rA0 = *(const float4*)(Ap0);
    rA1 = *(const float4*)(Ap1);
    rB0 = *(const float4*)(Bp0);
    rB1 = *(const float4*)(Bp1);
    stage(0, rA0, rA1, rB0, rB1);
    __syncthreads();

    float acc[2][2][4];
#pragma unroll
    for (int i = 0; i < 2; i++)
#pragma unroll
        for (int j = 0; j < 2; j++)
#pragma unroll
            for (int r = 0; r < 4; r++) acc[i][j][r] = 0.f;

#pragma unroll
    for (int tile = 0; tile < 8; tile++) {
        int buf = tile & 1;
        if (tile < 7) {
            int kb = (tile + 1) * 32;
            rA0 = *(const float4*)(Ap0 + kb);
            rA1 = *(const float4*)(Ap1 + kb);
            rB0 = *(const float4*)(Bp0 + kb);
            rB1 = *(const float4*)(Bp1 + kb);
        }
        const uint32_t* AH = smx[buf][0];
        const uint32_t* AL = smx[buf][1];
        const uint32_t* BH = smx[buf][2];
        const uint32_t* BL = smx[buf][3];
#pragma unroll
        for (int k2b = 0; k2b < 16; k2b += 8) {
            uint32_t ah[2][4], al[2][4], bh[2][2], bl[2][2];
#pragma unroll
            for (int mt = 0; mt < 2; mt++) {
                int i0 = (wm * 32 + mt * 16 + g) * 20 + k2b + tg;
                ah[mt][0] = AH[i0];       al[mt][0] = AL[i0];
                ah[mt][1] = AH[i0 + 160]; al[mt][1] = AL[i0 + 160];
                ah[mt][2] = AH[i0 + 4];   al[mt][2] = AL[i0 + 4];
                ah[mt][3] = AH[i0 + 164]; al[mt][3] = AL[i0 + 164];
            }
#pragma unroll
            for (int nt = 0; nt < 2; nt++) {
                int j0 = (wn * 16 + nt * 8 + g) * 20 + k2b + tg;
                bh[nt][0] = BH[j0];     bl[nt][0] = BL[j0];
                bh[nt][1] = BH[j0 + 4]; bl[nt][1] = BL[j0 + 4];
            }
#pragma unroll
            for (int mt = 0; mt < 2; mt++)
#pragma unroll
                for (int nt = 0; nt < 2; nt++) {
                    mma16(acc[mt][nt], ah[mt], bh[nt]);
                    mma16(acc[mt][nt], ah[mt], bl[nt]);
                    mma16(acc[mt][nt], al[mt], bh[nt]);
                }
        }
        if (tile < 7) {
            stage(buf ^ 1, rA0, rA1, rB0, rB1);
            __syncthreads();
        }
    }

    __syncthreads();
    float* eps = (float*)&smx[0][0][0];
#pragma unroll
    for (int mt = 0; mt < 2; mt++)
#pragma unroll
        for (int nt = 0; nt < 2; nt++) {
            int row0 = wm * 32 + mt * 16 + g;
            int col0 = wn * 16 + nt * 8 + 2 * tg;
            eps[col0 * 68 + row0]           = acc[mt][nt][0];
            eps[(col0 + 1) * 68 + row0]     = acc[mt][nt][1];
            eps[col0 * 68 + row0 + 8]       = acc[mt][nt][2];
            eps[(col0 + 1) * 68 + row0 + 8] = acc[mt][nt][3];
        }
    __syncthreads();
    {
        int mg = (tid & 15) * 4;
        int nr = tid >> 4;
#pragma unroll
        for (int pass = 0; pass < 4; pass++) {
            int n = pass * 16 + nr;
            float4 v = *(const float4*)&eps[n * 68 + mg];
            *(float4*)(Cm + (size_t)(bn + n) * MM + bm + mg) = v;
        }
    }
}

__global__ void k_gemm_qkv(const float* __restrict__ A) {
    gemm_mma_body<768>(A, g_sf, g_qkvt);
}
__global__ void k_gemm_proj(const float* __restrict__ A) {
    gemm_mma_body<256>(A, g_tmp, g_sfa);
}

// ------------------------------ K5: attention -------------------------------
#define K5_KV   (256 * 36)
#define K5_SMEM ((2 * K5_KV + 9 * 32) * 4)

__global__ void k_attn(const float* __restrict__ w_pe) {
    extern __shared__ float sm5[];
    float* k_s = sm5;
    float* v_s = k_s + K5_KV;
    float* wpe = v_s + K5_KV;

    int bx = blockIdx.x;
    int b = bx >> 5;
    int h = (bx >> 2) & 7;
    int qq = bx & 3;
    int tid = threadIdx.x;

    const float* base = g_qkvt + (size_t)b * NT * 768 + h * 96;
#pragma unroll
    for (int i = 0; i < 16; i++) {
        int f = tid + i * 128;
        int m = f >> 3, dq = (f & 7) * 4;
        float4 kv = *(const float4*)(base + (size_t)m * 768 + 32 + dq);
        float4 vv = *(const float4*)(base + (size_t)m * 768 + 64 + dq);
        *(float4*)&k_s[m * 36 + dq] = kv;
        *(float4*)&v_s[m * 36 + dq] = vv;
    }
    for (int idx = tid; idx < 288; idx += 128) {
        int d = idx & 31, k = idx >> 5;
        wpe[k * 32 + d] = w_pe[(h * 32 + d) * 9 + k];
    }
    __syncthreads();

    int j = qq * 64 + (tid >> 1);
    int e = tid & 1;
    int dh = e * 16;
    float q[16];
#pragma unroll
    for (int i = 0; i < 4; i++) {
        float4 qv = *(const float4*)(base + (size_t)j * 768 + dh + i * 4);
        q[4 * i + 0] = qv.x * ATTN_SCALE; q[4 * i + 1] = qv.y * ATTN_SCALE;
        q[4 * i + 2] = qv.z * ATTN_SCALE; q[4 * i + 3] = qv.w * ATTN_SCALE;
    }

    float o[16];
#pragma unroll
    for (int d = 0; d < 16; d++) o[d] = 0.f;
    float mx = -1e30f, l = 0.f;

    for (int m0 = 0; m0 < 256; m0 += 8) {
        float sc[8];
        float cmax = -1e30f;
#pragma unroll
        for (int mm = 0; mm < 8; mm++) {
            const float* kr = k_s + (m0 + mm) * 36 + dh;
            float s = 0.f;
#pragma unroll
            for (int i = 0; i < 4; i++) {
                float4 kv = *(const float4*)(kr + 4 * i);
                s += q[4 * i + 0] * kv.x + q[4 * i + 1] * kv.y
                   + q[4 * i + 2] * kv.z + q[4 * i + 3] * kv.w;
            }
            s += __shfl_xor_sync(0xffffffffu, s, 1);
            sc[mm] = s;
            cmax = fmaxf(cmax, s);
        }
        float nm = fmaxf(mx, cmax);
        float corr = __expf(mx - nm);
        l *= corr;
#pragma unroll
        for (int d = 0; d < 16; d++) o[d] *= corr;
        float p[8];
#pragma unroll
        for (int i = 0; i < 4; i++) {
            float sown = e ? sc[2 * i + 1] : sc[2 * i];
            float pown = __expf(sown - nm);
            float poth = __shfl_xor_sync(0xffffffffu, pown, 1);
            p[2 * i]     = e ? poth : pown;
            p[2 * i + 1] = e ? pown : poth;
        }
#pragma unroll
        for (int mm = 0; mm < 8; mm++) {
            float pv = p[mm];
            l += pv;
            const float* vr = v_s + (m0 + mm) * 36 + dh;
#pragma unroll
            for (int i = 0; i < 4; i++) {
                float4 vv = *(const float4*)(vr + 4 * i);
                o[4 * i + 0] += pv * vv.x; o[4 * i + 1] += pv * vv.y;
                o[4 * i + 2] += pv * vv.z; o[4 * i + 3] += pv * vv.w;
            }
        }
        mx = nm;
    }
    float invl = 1.f / l;

    int y = j >> 4, xx = j & 15;
    float* outp = g_tmp + ((size_t)(b * NT + j)) * Cc + h * 32 + dh;
#pragma unroll
    for (int i = 0; i < 4; i++) {
        float pe0 = 0.f, pe1 = 0.f, pe2 = 0.f, pe3 = 0.f;
#pragma unroll
        for (int u = 0; u < 3; u++) {
            int ny = y + u - 1;
            if ((unsigned)ny >= GG) continue;
#pragma unroll
            for (int v = 0; v < 3; v++) {
                int nx = xx + v - 1;
                if ((unsigned)nx >= GG) continue;
                int k = u * 3 + v;
                float4 w4 = *(const float4*)&wpe[k * 32 + dh + 4 * i];
                float4 vv = *(const float4*)&v_s[(ny * 16 + nx) * 36 + dh + 4 * i];
                pe0 += w4.x * vv.x; pe1 += w4.y * vv.y;
                pe2 += w4.z * vv.z; pe3 += w4.w * vv.w;
            }
        }
        float4 r;
        r.x = o[4 * i + 0] * invl + pe0;
        r.y = o[4 * i + 1] * invl + pe1;
        r.z = o[4 * i + 2] * invl + pe2;
        r.w = o[4 * i + 3] * invl + pe3;
        *(float4*)(outp + 4 * i) = r;
    }
}

// ------------------------------ K7: scatter ---------------------------------
__global__ void k_scatter(float* __restrict__ out) {
    __shared__ float s9[9 * 256];
    __shared__ float aff_s[64 * 12];
    int bt = blockIdx.x;
    int b = bt >> 8, t = bt & 255;
    int ty = t >> 4, tx = t & 15;
    int tid = threadIdx.x;

    for (int idx = tid; idx < 9 * 256; idx += 256) {
        int k = idx >> 8, c = idx & 255;
        int ny = ty + k / 3 - 1, nx = tx + k % 3 - 1;
        s9[idx] = ((unsigned)ny < GG && (unsigned)nx < GG)
                      ? g_sfa[(size_t)(b * NT + ny * GG + nx) * Cc + c]
                      : 0.f;
    }
    for (int idx = tid; idx < 576; idx += 256) {
        int p = idx / 9, k = idx - p * 9;
        aff_s[p * 12 + k] = g_aff[bt * 576 + idx];
    }
    __syncthreads();

    int squad = tid & 15;
    int cq = (tid >> 4) & 3;
    int pg = tid >> 6;

    float4 rk[9];
#pragma unroll
    for (int k = 0; k < 9; k++)
        rk[k] = *(const float4*)&s9[k * 256 + cq * 64 + squad * 4];

    int sy = squad >> 1, sxb = (squad & 1) * 4;
    float* opb = out + (size_t)b * Cc * HW + (ty * 8 + sy) * 128 + tx * 8 + sxb;

#pragma unroll
    for (int i = 0; i < 16; i++) {
        int p = pg * 16 + i;
        float4 afa = *(const float4*)&aff_s[p * 12];
        float4 afb = *(const float4*)&aff_s[p * 12 + 4];
        float af8 = aff_s[p * 12 + 8];
        float4 acc;
        acc.x = afa.x * rk[0].x; acc.y = afa.x * rk[0].y;
        acc.z = afa.x * rk[0].z; acc.w = afa.x * rk[0].w;
        acc.x += afa.y * rk[1].x; acc.y += afa.y * rk[1].y;
        acc.z += afa.y * rk[1].z; acc.w += afa.y * rk[1].w;
        acc.x += afa.z * rk[2].x; acc.y += afa.z * rk[2].y;
        acc.z += afa.z * rk[2].z; acc.w += afa.z * rk[2].w;
        acc.x += afa.w * rk[3].x; acc.y += afa.w * rk[3].y;
        acc.z += afa.w * rk[3].z; acc.w += afa.w * rk[3].w;
        acc.x += afb.x * rk[4].x; acc.y += afb.x * rk[4].y;
        acc.z += afb.x * rk[4].z; acc.w += afb.x * rk[4].w;
        acc.x += afb.y * rk[5].x; acc.y += afb.y * rk[5].y;
        acc.z += afb.y * rk[5].z; acc.w += afb.y * rk[5].w;
        acc.x += afb.z * rk[6].x; acc.y += afb.z * rk[6].y;
        acc.z += afb.z * rk[6].z; acc.w += afb.z * rk[6].w;
        acc.x += afb.w * rk[7].x; acc.y += afb.w * rk[7].y;
        acc.z += afb.w * rk[7].z; acc.w += afb.w * rk[7].w;
        acc.x += af8 * rk[8].x; acc.y += af8 * rk[8].y;
        acc.z += af8 * rk[8].z; acc.w += af8 * rk[8].w;
        int c = p * 4 + cq;
        *(float4*)(opb + (size_t)c * HW) = acc;
    }
}

// ------------------------------- launcher -----------------------------------
extern "C" void kernel_launch(void* const* d_in, const int* in_sizes, int n_in,
                              void* d_out, int out_size) {
    (void)in_sizes; (void)n_in; (void)out_size;
    const float* x      = (const float*)d_in[0];
    const float* w_qkv  = (const float*)d_in[1];
    const float* w_pe   = (const float*)d_in[2];
    const float* w_proj = (const float*)d_in[3];
    float* out = (float*)d_out;

    cudaFuncSetAttribute(k_aff, cudaFuncAttributeMaxDynamicSharedMemorySize, KA_SMEM);
    cudaFuncSetAttribute(k_attn, cudaFuncAttributeMaxDynamicSharedMemorySize, K5_SMEM);

    k_pool<<<NTOK, 256>>>(x);
    k_aff<<<NTOK, 256, KA_SMEM>>>(x);
    k_fold<<<NTOK, 256>>>();
    k_gemm_qkv<<<dim3(12, 32), 256>>>(w_qkv);
    k_attn<<<256, 128, K5_SMEM>>>(w_pe);
    k_gemm_proj<<<dim3(4, 32), 256>>>(w_proj);
    k_scatter<<<NTOK, 256>>>(out);
}

// round 15
// speedup vs baseline: 1.0094x; 1.0094x over previous
#include <cuda_runtime.h>
#include <cstddef>
#include <cstdint>

// ---------------------------------------------------------------------------
// StokenAttention: B=8, C=256, H=W=128, 8x8 super-tokens -> 16x16 grid,
// NH=8 heads, HD=KD=32.
// GEMMs (qkv, proj) AND k_aff's two per-token GEMMs on mma.sync m16n8k16
// bf16 hi/lo (fp32-like accuracy). k_aff G1 B-operand via ldmatrix.trans.
// ---------------------------------------------------------------------------

#define Bb 8
#define Cc 256
#define GG 16
#define NT 256
#define NP 64
#define HW 16384
#define NH 8
#define HD 32
#define NTOK (Bb * NT)

__device__ float g_stoken[NTOK * Cc];
__device__ float g_aff[NTOK * NP * 9];
__device__ float g_asum[NTOK * 9];
__device__ float g_M[(size_t)NTOK * 9 * Cc];
__device__ float g_sf[NTOK * Cc];
__device__ float g_qkvt[(size_t)NTOK * 768];     // [tok][o] token-major
__device__ float g_tmp[NTOK * Cc];
__device__ float g_sfa[NTOK * Cc];

#define AFF_SCALE 0.0625f
#define ATTN_SCALE 0.17677669529663687f

// --------------------------- bf16 mma helpers ------------------------------
__device__ __forceinline__ void pack2(float x, float y, uint32_t& h, uint32_t& lo) {
    asm("cvt.rn.bf16x2.f32 %0, %1, %2;" : "=r"(h) : "f"(y), "f"(x));
    float xh = __uint_as_float(h << 16);
    float yh = __uint_as_float(h & 0xFFFF0000u);
    float xl = x - xh, yl = y - yh;
    asm("cvt.rn.bf16x2.f32 %0, %1, %2;" : "=r"(lo) : "f"(yl), "f"(xl));
}
__device__ __forceinline__ void splitbf(float v, uint16_t& h, uint16_t& lo) {
    asm("cvt.rn.bf16.f32 %0, %1;" : "=h"(h) : "f"(v));
    float vh = __uint_as_float((uint32_t)h << 16);
    asm("cvt.rn.bf16.f32 %0, %1;" : "=h"(lo) : "f"(v - vh));
}
__device__ __forceinline__ void mma16(float* c, const uint32_t* a, const uint32_t* b) {
    asm volatile(
        "mma.sync.aligned.m16n8k16.row.col.f32.bf16.bf16.f32 "
        "{%0,%1,%2,%3}, {%4,%5,%6,%7}, {%8,%9}, {%0,%1,%2,%3};"
        : "+f"(c[0]), "+f"(c[1]), "+f"(c[2]), "+f"(c[3])
        : "r"(a[0]), "r"(a[1]), "r"(a[2]), "r"(a[3]), "r"(b[0]), "r"(b[1]));
}
__device__ __forceinline__ void ldsm_x2_t(uint32_t& r0, uint32_t& r1, uint32_t addr) {
    asm volatile("ldmatrix.sync.aligned.m8n8.x2.trans.shared.b16 {%0,%1}, [%2];"
                 : "=r"(r0), "=r"(r1) : "r"(addr));
}
__device__ __forceinline__ uint32_t smem_u32(const void* p) {
    uint32_t a;
    asm("{ .reg .u64 t; cvta.to.shared.u64 t, %1; cvt.u32.u64 %0, t; }"
        : "=r"(a) : "l"(p));
    return a;
}

// ------------------------------- K1: pooling -------------------------------
__global__ void k_pool(const float* __restrict__ x) {
    int bt = blockIdx.x;
    int t = bt & 255;
    int ty = t >> 4, tx = t & 15;
    int c = threadIdx.x;
    const float* xp = x + (size_t)(((bt >> 8) * Cc + c)) * HW + (ty * 8) * 128 + tx * 8;
    float s = 0.f;
#pragma unroll
    for (int i = 0; i < 8; i++) {
        float4 a = *(const float4*)(xp + i * 128);
        float4 b4 = *(const float4*)(xp + i * 128 + 4);
        s += a.x + a.y + a.z + a.w + b4.x + b4.y + b4.z + b4.w;
    }
    g_stoken[bt * Cc + c] = s * (1.0f / 64.0f);
}

// ------------------------- K2: affinity + token GEMM (tensor) ---------------
// smem word offsets
#define KA_PIXH 0            // pix bf16-hi [c=256][p2=32] stride 36
#define KA_PIXL 9216
#define KA_ST9H 18432        // st9 bf16-hi [k=16][c2=128] stride 132
#define KA_ST9L 20544
#define KA_SM   22656        // S fp32 [p=64][k] stride 17
#define KA_AFF  23744        // aff fp32 [p=64][12]
#define KA_AFTH 24512        // affT bf16-hi [k=16][p2=32] stride 36
#define KA_AFTL 25088
#define KA_WORDS 25664
#define KA_SMEM (KA_WORDS * 4)

__global__ void k_aff(const float* __restrict__ x) {
    extern __shared__ uint32_t dsm[];
    uint32_t sbase = smem_u32(dsm);

    int bt = blockIdx.x;
    int b = bt >> 8, t = bt & 255;
    int ty = t >> 4, tx = t & 15;
    int tid = threadIdx.x;
    int w = tid >> 5, l = tid & 31;
    int g = l >> 2, tg = l & 3;

    // --- stage st9 as A operand [k16][c2], rows 9..15 zero ---
    for (int i = tid; i < 16 * 128; i += 256) {
        int k = i >> 7, c2 = i & 127;
        float v0 = 0.f, v1 = 0.f;
        if (k < 9) {
            int ny = ty + k / 3 - 1, nx = tx + k % 3 - 1;
            if ((unsigned)ny < GG && (unsigned)nx < GG) {
                const float* sp = g_stoken + (size_t)(b * NT + ny * GG + nx) * Cc + 2 * c2;
                v0 = sp[0]; v1 = sp[1];
            }
        }
        uint32_t h, lo;
        pack2(v0, v1, h, lo);
        dsm[KA_ST9H + k * 132 + c2] = h;
        dsm[KA_ST9L + k * 132 + c2] = lo;
    }
    // --- stage pix as [c][p2] bf16 hi/lo (sector-optimal loads) ---
    const float* xb = x + (size_t)b * Cc * HW + (ty * 8) * 128 + tx * 8;
#pragma unroll
    for (int it = 0; it < 16; it++) {
        int idx = tid + it * 256;
        int c = idx >> 4;
        int q = idx & 15;
        int sy = q >> 1, hx = q & 1;
        float4 v = *(const float4*)(xb + (size_t)c * HW + sy * 128 + hx * 4);
        int p2 = (sy * 8 + hx * 4) >> 1;
        uint32_t h, lo;
        pack2(v.x, v.y, h, lo);
        dsm[KA_PIXH + c * 36 + p2] = h;
        dsm[KA_PIXL + c * 36 + p2] = lo;
        pack2(v.z, v.w, h, lo);
        dsm[KA_PIXH + c * 36 + p2 + 1] = h;
        dsm[KA_PIXL + c * 36 + p2 + 1] = lo;
    }
    __syncthreads();

    // --- G1: C[k16][p64] = st9 x pix^T; warp w owns p-range [8w, 8w+8) ---
    {
        float accS[4] = {0.f, 0.f, 0.f, 0.f};
        int lrow = l & 15;
        uint32_t ldh = sbase + (uint32_t)(KA_PIXH + lrow * 36) * 4 + (8 * w) * 2;
        uint32_t ldl = ldh + (uint32_t)(KA_PIXL - KA_PIXH) * 4;
#pragma unroll
        for (int kt = 0; kt < 16; kt++) {
            uint32_t ah[4], al[4], bh[2], bl[2];
            int i0 = g * 132 + kt * 8 + tg;
            ah[0] = dsm[KA_ST9H + i0];        ah[1] = dsm[KA_ST9H + i0 + 1056];
            ah[2] = dsm[KA_ST9H + i0 + 4];    ah[3] = dsm[KA_ST9H + i0 + 1060];
            al[0] = dsm[KA_ST9L + i0];        al[1] = dsm[KA_ST9L + i0 + 1056];
            al[2] = dsm[KA_ST9L + i0 + 4];    al[3] = dsm[KA_ST9L + i0 + 1060];
            ldsm_x2_t(bh[0], bh[1], ldh + (uint32_t)kt * 16 * 144);
            ldsm_x2_t(bl[0], bl[1], ldl + (uint32_t)kt * 16 * 144);
            mma16(accS, ah, bh);
            mma16(accS, ah, bl);
            mma16(accS, al, bh);
        }
        float* Sm = (float*)(dsm + KA_SM);
        int pb = 8 * w + 2 * tg;
        Sm[pb * 17 + g] = accS[0];
        Sm[(pb + 1) * 17 + g] = accS[1];
        Sm[pb * 17 + g + 8] = accS[2];
        Sm[(pb + 1) * 17 + g + 8] = accS[3];
    }
    __syncthreads();

    // --- softmax per pixel + affT staging; zero affT rows 9..15 ---
    if (tid < 64) {
        float* Sm = (float*)(dsm + KA_SM);
        float* afff = (float*)(dsm + KA_AFF);
        uint16_t* ath = (uint16_t*)(dsm + KA_AFTH);
        uint16_t* atl = (uint16_t*)(dsm + KA_AFTL);
        float v[9];
        float mx = -1e30f;
#pragma unroll
        for (int k = 0; k < 9; k++) { v[k] = Sm[tid * 17 + k] * AFF_SCALE; mx = fmaxf(mx, v[k]); }
        float sum = 0.f;
#pragma unroll
        for (int k = 0; k < 9; k++) { v[k] = __expf(v[k] - mx); sum += v[k]; }
        float inv = 1.f / sum;
#pragma unroll
        for (int k = 0; k < 9; k++) {
            float a = v[k] * inv;
            afff[tid * 12 + k] = a;
            uint16_t hh, lo;
            splitbf(a, hh, lo);
            ath[k * 72 + tid] = hh;
            atl[k * 72 + tid] = lo;
        }
    } else {
        for (int i = tid - 64; i < 7 * 36; i += 192) {
            dsm[KA_AFTH + 9 * 36 + i] = 0;
            dsm[KA_AFTL + 9 * 36 + i] = 0;
        }
    }
    __syncthreads();

    // --- outputs: g_aff, g_asum ---
    {
        float* afff = (float*)(dsm + KA_AFF);
        for (int idx = tid; idx < 576; idx += 256) {
            int p = idx / 9, k = idx - p * 9;
            g_aff[bt * 576 + idx] = afff[p * 12 + k];
        }
        if (tid < 9) {
            float s = 0.f;
            for (int p = 0; p < 64; p++) s += afff[p * 12 + tid];
            g_asum[bt * 9 + tid] = s;
        }
    }

    // --- G2: M[k16][c256] = affT x pix; warp w owns c-range [32w, 32w+32) ---
    {
        uint32_t Ah[4][4], Al[4][4];
#pragma unroll
        for (int kt = 0; kt < 4; kt++) {
            int i0 = g * 36 + kt * 8 + tg;
            Ah[kt][0] = dsm[KA_AFTH + i0];       Ah[kt][1] = dsm[KA_AFTH + i0 + 288];
            Ah[kt][2] = dsm[KA_AFTH + i0 + 4];   Ah[kt][3] = dsm[KA_AFTH + i0 + 292];
            Al[kt][0] = dsm[KA_AFTL + i0];       Al[kt][1] = dsm[KA_AFTL + i0 + 288];
            Al[kt][2] = dsm[KA_AFTL + i0 + 4];   Al[kt][3] = dsm[KA_AFTL + i0 + 292];
        }
        float* Mo = g_M + (size_t)bt * 9 * Cc;
#pragma unroll
        for (int j = 0; j < 4; j++) {
            int cb = 32 * w + 8 * j;
            float acc[4] = {0.f, 0.f, 0.f, 0.f};
#pragma unroll
            for (int kt = 0; kt < 4; kt++) {
                uint32_t bh[2], bl[2];
                int bi = (cb + g) * 36 + kt * 8 + tg;
                bh[0] = dsm[KA_PIXH + bi]; bh[1] = dsm[KA_PIXH + bi + 4];
                bl[0] = dsm[KA_PIXL + bi]; bl[1] = dsm[KA_PIXL + bi + 4];
                mma16(acc, Ah[kt], bh);
                mma16(acc, Ah[kt], bl);
                mma16(acc, Al[kt], bh);
            }
            float2 v01; v01.x = acc[0]; v01.y = acc[1];
            *(float2*)(Mo + g * Cc + cb + 2 * tg) = v01;
            if (g == 0) {
                float2 v23; v23.x = acc[2]; v23.y = acc[3];
                *(float2*)(Mo + 8 * Cc + cb + 2 * tg) = v23;
            }
        }
    }
}

// ------------------------------- K3: fold ----------------------------------
__global__ void k_fold() {
    int bt = blockIdx.x;
    int b = bt >> 8, t = bt & 255;
    int y = t >> 4, x = t & 15;
    __shared__ float s_as;
    int tid = threadIdx.x;
    if (tid == 0) {
        float s = 0.f;
        for (int ny = y - 1; ny <= y + 1; ny++)
            for (int nx = x - 1; nx <= x + 1; nx++)
                if ((unsigned)ny < GG && (unsigned)nx < GG) {
                    int k = (y - ny + 1) * 3 + (x - nx + 1);
                    s += g_asum[(b * NT + ny * GG + nx) * 9 + k];
                }
        s_as = s + 1e-12f;
    }
    __syncthreads();
    int c = tid;
    float s = 0.f;
    for (int ny = y - 1; ny <= y + 1; ny++)
        for (int nx = x - 1; nx <= x + 1; nx++)
            if ((unsigned)ny < GG && (unsigned)nx < GG) {
                int k = (y - ny + 1) * 3 + (x - nx + 1);
                s += g_M[((size_t)(b * NT + ny * GG + nx) * 9 + k) * Cc + c];
            }
    g_sf[bt * Cc + c] = s / s_as;
}

// ---------- GEMM via mma.sync m16n8k16 bf16 (hi/lo, token-major out) --------
template <int MM>
__device__ __forceinline__ void gemm_mma_body(const float* __restrict__ A,
                                              const float* __restrict__ Bm,
                                              float* __restrict__ Cm) {
    const int K = 256;
    __shared__ uint32_t smx[2][4][1280];

    int bm = blockIdx.x * 64;
    int bn = blockIdx.y * 64;
    int tid = threadIdx.x;
    int w = tid >> 5, l = tid & 31;
    int wm = w >> 2, wn = w & 3;
    int g = l >> 2, tg = l & 3;

    int r0 = tid >> 3, r1 = r0 + 32;
    int k0q = (tid & 7) * 4;
    int k2s = k0q >> 1;

    const float* Ap0 = A + (size_t)(bm + r0) * K + k0q;
    const float* Ap1 = A + (size_t)(bm + r1) * K + k0q;
    const float* Bp0 = Bm + (size_t)(bn + r0) * K + k0q;
    const float* Bp1 = Bm + (size_t)(bn + r1) * K + k0q;

    float4 rA0, rA1, rB0, rB1;

    auto stage = [&](int buf, const float4& a0v, const float4& a1v,
                     const float4& b0v, const float4& b1v) {
        uint32_t h0, l0, h1, l1;
        pack2(a0v.x, a0v.y, h0, l0); pack2(a0v.z, a0v.w, h1, l1);
        *(uint2*)&smx[buf][0][r0 * 20 + k2s] = make_uint2(h0, h1);
        *(uint2*)&smx[buf][1][r0 * 20 + k2s] = make_uint2(l0, l1);
        pack2(a1v.x, a1v.y, h0, l0); pack2(a1v.z, a1v.w, h1, l1);
        *(uint2*)&smx[buf][0][r1 * 20 + k2s] = make_uint2(h0, h1);
        *(uint2*)&smx[buf][1][r1 * 20 + k2s] = make_uint2(l0, l1);
        pack2(b0v.x, b0v.y, h0, l0); pack2(b0v.z, b0v.w, h1, l1);
        *(uint2*)&smx[buf][2][r0 * 20 + k2s] = make_uint2(h0, h1);
        *(uint2*)&smx[buf][3][r0 * 20 + k2s] = make_uint2(l0, l1);
        pack2(b1v.x, b1v.y, h0, l0); pack2(b1v.z, b1v.w, h1, l1);
        *(uint2*)&smx[buf][2][r1 * 20 + k2s] = make_uint2(h0, h1);
        *(uint2*)&smx[buf][3][r1 * 20 + k2s] = make_uint2(l0, l1);
    };

    rA0 = *(const float4*)(Ap0);
    rA1 = *(const float4*)(Ap1);
    rB0 = *(const float4*)(Bp0);
    rB1 = *(const float4*)(Bp1);
    stage(0, rA0, rA1, rB0, rB1);
    __syncthreads();

    float acc[2][2][4];
#pragma unroll
    for (int i = 0; i < 2; i++)
#pragma unroll
        for (int j = 0; j < 2; j++)
#pragma unroll
            for (int r = 0; r < 4; r++) acc[i][j][r] = 0.f;

#pragma unroll
    for (int tile = 0; tile < 8; tile++) {
        int buf = tile & 1;
        if (tile < 7) {
            int kb = (tile + 1) * 32;
            rA0 = *(const float4*)(Ap0 + kb);
            rA1 = *(const float4*)(Ap1 + kb);
            rB0 = *(const float4*)(Bp0 + kb);
            rB1 = *(const float4*)(Bp1 + kb);
        }
        const uint32_t* AH = smx[buf][0];
        const uint32_t* AL = smx[buf][1];
        const uint32_t* BH = smx[buf][2];
        const uint32_t* BL = smx[buf][3];
#pragma unroll
        for (int k2b = 0; k2b < 16; k2b += 8) {
            uint32_t ah[2][4], al[2][4], bh[2][2], bl[2][2];
#pragma unroll
            for (int mt = 0; mt < 2; mt++) {
                int i0 = (wm * 32 + mt * 16 + g) * 20 + k2b + tg;
                ah[mt][0] = AH[i0];       al[mt][0] = AL[i0];
                ah[mt][1] = AH[i0 + 160]; al[mt][1] = AL[i0 + 160];
                ah[mt][2] = AH[i0 + 4];   al[mt][2] = AL[i0 + 4];
                ah[mt][3] = AH[i0 + 164]; al[mt][3] = AL[i0 + 164];
            }
#pragma unroll
            for (int nt = 0; nt < 2; nt++) {
                int j0 = (wn * 16 + nt * 8 + g) * 20 + k2b + tg;
                bh[nt][0] = BH[j0];     bl[nt][0] = BL[j0];
                bh[nt][1] = BH[j0 + 4]; bl[nt][1] = BL[j0 + 4];
            }
#pragma unroll
            for (int mt = 0; mt < 2; mt++)
#pragma unroll
                for (int nt = 0; nt < 2; nt++) {
                    mma16(acc[mt][nt], ah[mt], bh[nt]);
                    mma16(acc[mt][nt], ah[mt], bl[nt]);
                    mma16(acc[mt][nt], al[mt], bh[nt]);
                }
        }
        if (tile < 7) {
            stage(buf ^ 1, rA0, rA1, rB0, rB1);
            __syncthreads();
        }
    }

    __syncthreads();
    float* eps = (float*)&smx[0][0][0];
#pragma unroll
    for (int mt = 0; mt < 2; mt++)
#pragma unroll
        for (int nt = 0; nt < 2; nt++) {
            int row0 = wm * 32 + mt * 16 + g;
            int col0 = wn * 16 + nt * 8 + 2 * tg;
            eps[col0 * 68 + row0]           = acc[mt][nt][0];
            eps[(col0 + 1) * 68 + row0]     = acc[mt][nt][1];
            eps[col0 * 68 + row0 + 8]       = acc[mt][nt][2];
            eps[(col0 + 1) * 68 + row0 + 8] = acc[mt][nt][3];
        }
    __syncthreads();
    {
        int mg = (tid & 15) * 4;
        int nr = tid >> 4;
#pragma unroll
        for (int pass = 0; pass < 4; pass++) {
            int n = pass * 16 + nr;
            float4 v = *(const float4*)&eps[n * 68 + mg];
            *(float4*)(Cm + (size_t)(bn + n) * MM + bm + mg) = v;
        }
    }
}

__global__ void k_gemm_qkv(const float* __restrict__ A) {
    gemm_mma_body<768>(A, g_sf, g_qkvt);
}
__global__ void k_gemm_proj(const float* __restrict__ A) {
    gemm_mma_body<256>(A, g_tmp, g_sfa);
}

// ------------------------------ K5: attention -------------------------------
#define K5_KV   (256 * 36)
#define K5_SMEM ((2 * K5_KV + 9 * 32) * 4)

__global__ void k_attn(const float* __restrict__ w_pe) {
    extern __shared__ float sm5[];
    float* k_s = sm5;
    float* v_s = k_s + K5_KV;
    float* wpe = v_s + K5_KV;

    int bx = blockIdx.x;
    int b = bx >> 5;
    int h = (bx >> 2) & 7;
    int qq = bx & 3;
    int tid = threadIdx.x;

    const float* base = g_qkvt + (size_t)b * NT * 768 + h * 96;
#pragma unroll
    for (int i = 0; i < 16; i++) {
        int f = tid + i * 128;
        int m = f >> 3, dq = (f & 7) * 4;
        float4 kv = *(const float4*)(base + (size_t)m * 768 + 32 + dq);
        float4 vv = *(const float4*)(base + (size_t)m * 768 + 64 + dq);
        *(float4*)&k_s[m * 36 + dq] = kv;
        *(float4*)&v_s[m * 36 + dq] = vv;
    }
    for (int idx = tid; idx < 288; idx += 128) {
        int d = idx & 31, k = idx >> 5;
        wpe[k * 32 + d] = w_pe[(h * 32 + d) * 9 + k];
    }
    __syncthreads();

    int j = qq * 64 + (tid >> 1);
    int e = tid & 1;
    int dh = e * 16;
    float q[16];
#pragma unroll
    for (int i = 0; i < 4; i++) {
        float4 qv = *(const float4*)(base + (size_t)j * 768 + dh + i * 4);
        q[4 * i + 0] = qv.x * ATTN_SCALE; q[4 * i + 1] = qv.y * ATTN_SCALE;
        q[4 * i + 2] = qv.z * ATTN_SCALE; q[4 * i + 3] = qv.w * ATTN_SCALE;
    }

    float o[16];
#pragma unroll
    for (int d = 0; d < 16; d++) o[d] = 0.f;
    float mx = -1e30f, l = 0.f;

    for (int m0 = 0; m0 < 256; m0 += 8) {
        float sc[8];
        float cmax = -1e30f;
#pragma unroll
        for (int mm = 0; mm < 8; mm++) {
            const float* kr = k_s + (m0 + mm) * 36 + dh;
            float s = 0.f;
#pragma unroll
            for (int i = 0; i < 4; i++) {
                float4 kv = *(const float4*)(kr + 4 * i);
                s += q[4 * i + 0] * kv.x + q[4 * i + 1] * kv.y
                   + q[4 * i + 2] * kv.z + q[4 * i + 3] * kv.w;
            }
            s += __shfl_xor_sync(0xffffffffu, s, 1);
            sc[mm] = s;
            cmax = fmaxf(cmax, s);
        }
        float nm = fmaxf(mx, cmax);
        float corr = __expf(mx - nm);
        l *= corr;
#pragma unroll
        for (int d = 0; d < 16; d++) o[d] *= corr;
        float p[8];
#pragma unroll
        for (int i = 0; i < 4; i++) {
            float sown = e ? sc[2 * i + 1] : sc[2 * i];
            float pown = __expf(sown - nm);
            float poth = __shfl_xor_sync(0xffffffffu, pown, 1);
            p[2 * i]     = e ? poth : pown;
            p[2 * i + 1] = e ? pown : poth;
        }
#pragma unroll
        for (int mm = 0; mm < 8; mm++) {
            float pv = p[mm];
            l += pv;
            const float* vr = v_s + (m0 + mm) * 36 + dh;
#pragma unroll
            for (int i = 0; i < 4; i++) {
                float4 vv = *(const float4*)(vr + 4 * i);
                o[4 * i + 0] += pv * vv.x; o[4 * i + 1] += pv * vv.y;
                o[4 * i + 2] += pv * vv.z; o[4 * i + 3] += pv * vv.w;
            }
        }
        mx = nm;
    }
    float invl = 1.f / l;

    int y = j >> 4, xx = j & 15;
    float* outp = g_tmp + ((size_t)(b * NT + j)) * Cc + h * 32 + dh;
#pragma unroll
    for (int i = 0; i < 4; i++) {
        float pe0 = 0.f, pe1 = 0.f, pe2 = 0.f, pe3 = 0.f;
#pragma unroll
        for (int u = 0; u < 3; u++) {
            int ny = y + u - 1;
            if ((unsigned)ny >= GG) continue;
#pragma unroll
            for (int v = 0; v < 3; v++) {
                int nx = xx + v - 1;
                if ((unsigned)nx >= GG) continue;
                int k = u * 3 + v;
                float4 w4 = *(const float4*)&wpe[k * 32 + dh + 4 * i];
                float4 vv = *(const float4*)&v_s[(ny * 16 + nx) * 36 + dh + 4 * i];
                pe0 += w4.x * vv.x; pe1 += w4.y * vv.y;
                pe2 += w4.z * vv.z; pe3 += w4.w * vv.w;
            }
        }
        float4 r;
        r.x = o[4 * i + 0] * invl + pe0;
        r.y = o[4 * i + 1] * invl + pe1;
        r.z = o[4 * i + 2] * invl + pe2;
        r.w = o[4 * i + 3] * invl + pe3;
        *(float4*)(outp + 4 * i) = r;
    }
}

// ------------------------------ K7: scatter ---------------------------------
__global__ void k_scatter(float* __restrict__ out) {
    __shared__ float s9[9 * 256];
    __shared__ float aff_s[64 * 12];
    int bt = blockIdx.x;
    int b = bt >> 8, t = bt & 255;
    int ty = t >> 4, tx = t & 15;
    int tid = threadIdx.x;

    for (int idx = tid; idx < 9 * 256; idx += 256) {
        int k = idx >> 8, c = idx & 255;
        int ny = ty + k / 3 - 1, nx = tx + k % 3 - 1;
        s9[idx] = ((unsigned)ny < GG && (unsigned)nx < GG)
                      ? g_sfa[(size_t)(b * NT + ny * GG + nx) * Cc + c]
                      : 0.f;
    }
    for (int idx = tid; idx < 576; idx += 256) {
        int p = idx / 9, k = idx - p * 9;
        aff_s[p * 12 + k] = g_aff[bt * 576 + idx];
    }
    __syncthreads();

    int squad = tid & 15;
    int cq = (tid >> 4) & 3;
    int pg = tid >> 6;

    float4 rk[9];
#pragma unroll
    for (int k = 0; k < 9; k++)
        rk[k] = *(const float4*)&s9[k * 256 + cq * 64 + squad * 4];

    int sy = squad >> 1, sxb = (squad & 1) * 4;
    float* opb = out + (size_t)b * Cc * HW + (ty * 8 + sy) * 128 + tx * 8 + sxb;

#pragma unroll
    for (int i = 0; i < 16; i++) {
        int p = pg * 16 + i;
        float4 afa = *(const float4*)&aff_s[p * 12];
        float4 afb = *(const float4*)&aff_s[p * 12 + 4];
        float af8 = aff_s[p * 12 + 8];
        float4 acc;
        acc.x = afa.x * rk[0].x; acc.y = afa.x * rk[0].y;
        acc.z = afa.x * rk[0].z; acc.w = afa.x * rk[0].w;
        acc.x += afa.y * rk[1].x; acc.y += afa.y * rk[1].y;
        acc.z += afa.y * rk[1].z; acc.w += afa.y * rk[1].w;
        acc.x += afa.z * rk[2].x; acc.y += afa.z * rk[2].y;
        acc.z += afa.z * rk[2].z; acc.w += afa.z * rk[2].w;
        acc.x += afa.w * rk[3].x; acc.y += afa.w * rk[3].y;
        acc.z += afa.w * rk[3].z; acc.w += afa.w * rk[3].w;
        acc.x += afb.x * rk[4].x; acc.y += afb.x * rk[4].y;
        acc.z += afb.x * rk[4].z; acc.w += afb.x * rk[4].w;
        acc.x += afb.y * rk[5].x; acc.y += afb.y * rk[5].y;
        acc.z += afb.y * rk[5].z; acc.w += afb.y * rk[5].w;
        acc.x += afb.z * rk[6].x; acc.y += afb.z * rk[6].y;
        acc.z += afb.z * rk[6].z; acc.w += afb.z * rk[6].w;
        acc.x += afb.w * rk[7].x; acc.y += afb.w * rk[7].y;
        acc.z += afb.w * rk[7].z; acc.w += afb.w * rk[7].w;
        acc.x += af8 * rk[8].x; acc.y += af8 * rk[8].y;
        acc.z += af8 * rk[8].z; acc.w += af8 * rk[8].w;
        int c = p * 4 + cq;
        *(float4*)(opb + (size_t)c * HW) = acc;
    }
}

// ------------------------------- launcher -----------------------------------
extern "C" void kernel_launch(void* const* d_in, const int* in_sizes, int n_in,
                              void* d_out, int out_size) {
    (void)in_sizes; (void)n_in; (void)out_size;
    const float* x      = (const float*)d_in[0];
    const float* w_qkv  = (const float*)d_in[1];
    const float* w_pe   = (const float*)d_in[2];
    const float* w_proj = (const float*)d_in[3];
    float* out = (float*)d_out;

    cudaFuncSetAttribute(k_aff, cudaFuncAttributeMaxDynamicSharedMemorySize, KA_SMEM);
    cudaFuncSetAttribute(k_attn, cudaFuncAttributeMaxDynamicSharedMemorySize, K5_SMEM);

    k_pool<<<NTOK, 256>>>(x);
    k_aff<<<NTOK, 256, KA_SMEM>>>(x);
    k_fold<<<NTOK, 256>>>();
    k_gemm_qkv<<<dim3(12, 32), 256>>>(w_qkv);
    k_attn<<<256, 128, K5_SMEM>>>(w_pe);
    k_gemm_proj<<<dim3(4, 32), 256>>>(w_proj);
    k_scatter<<<NTOK, 256>>>(out);
}